// round 2
// baseline (speedup 1.0000x reference)
#include <cuda_runtime.h>
#include <math.h>

#define NB 2
#define NC 21
#define HH 64
#define WW 64
#define PP 4096
#define KS 71
#define KR 35

// ---------------- scratch (static device globals; no allocation) ----------------
__device__ float g_K[(size_t)NB * PP * PP];     // 134 MB, fp32, symmetric
__device__ float g_feat[NB * 5 * PP];           // [n][d][p] scaled features
__device__ float g_h[NB * PP];                  // -0.5*||f||^2
__device__ float g_U[NB * NC * PP];             // log(clip(unary))
__device__ float g_q[NB * NC * PP];             // current q
__device__ float g_qbf[NB * NC * PP];           // bilateral message
__device__ float g_qsf[NB * NC * PP];           // spatial message
__device__ float g_g1d[KS];                     // separable 1D gaussian

// ---------------- packed f32x2 FMA (2 MACs / inst) ----------------
__device__ __forceinline__ void fma2(float2& a, float bx, float by, float cx, float cy) {
    float2 b = make_float2(bx, by);
    float2 c = make_float2(cx, cy);
    unsigned long long* pa = reinterpret_cast<unsigned long long*>(&a);
    unsigned long long bb = *reinterpret_cast<unsigned long long*>(&b);
    unsigned long long cc = *reinterpret_cast<unsigned long long*>(&c);
    asm("fma.rn.f32x2 %0, %1, %2, %0;" : "+l"(*pa) : "l"(bb), "l"(cc));
}

// ---------------- prep: scaled features + h ----------------
__global__ void k_prep(const float* __restrict__ ref, const float* __restrict__ kstd) {
    int t = blockIdx.x * blockDim.x + threadIdx.x;
    if (t >= NB * PP) return;
    int n = t / PP, p = t % PP;
    int y = p >> 6, x = p & 63;
    float f[5];
    f[0] = (float)y / kstd[0];
    f[1] = (float)x / kstd[1];
    f[2] = ref[(n * 3 + 0) * PP + p] / kstd[2];
    f[3] = ref[(n * 3 + 1) * PP + p] / kstd[3];
    f[4] = ref[(n * 3 + 2) * PP + p] / kstd[4];
    float h = 0.f;
#pragma unroll
    for (int d = 0; d < 5; ++d) {
        g_feat[(n * 5 + d) * PP + p] = f[d];
        h = fmaf(f[d], f[d], h);
    }
    g_h[n * PP + p] = -0.5f * h;
}

// ---------------- prep: U = log(clip(unary, 1e-5, 1)) ----------------
__global__ void k_logU(const float* __restrict__ unary) {
    int t = blockIdx.x * blockDim.x + threadIdx.x;
    if (t >= NB * NC * PP) return;
    float u = unary[t];
    u = fminf(fmaxf(u, 1e-5f), 1.0f);
    g_U[t] = logf(u);
}

// ---------------- prep: extract separable 1D kernel from gk ----------------
__global__ void k_g1d(const float* __restrict__ gk) {
    __shared__ float s[128];
    int t = threadIdx.x;
    float v = (t < KS) ? gk[KR * KS + t] : 0.f;  // channel 0, center row
    s[t] = v;
    __syncthreads();
    for (int o = 64; o; o >>= 1) {
        if (t < o) s[t] += s[t + o];
        __syncthreads();
    }
    if (t < KS) g_g1d[t] = v / s[0];
}

// ---------------- build K (symmetric: upper-triangle tiles, smem transpose) ----------------
__global__ void k_buildK() {
    int bj = blockIdx.x, bi = blockIdx.y, n = blockIdx.z;
    if (bj < bi) return;  // triangle only
    __shared__ float sfi[5][64], sfj[5][64], shi[64], shj[64];
    __shared__ float tile[64][65];
    int tid = threadIdx.x;
    if (tid < 64) {
        int pi = bi * 64 + tid, pj = bj * 64 + tid;
#pragma unroll
        for (int d = 0; d < 5; ++d) {
            sfi[d][tid] = g_feat[(n * 5 + d) * PP + pi];
            sfj[d][tid] = g_feat[(n * 5 + d) * PP + pj];
        }
        shi[tid] = g_h[n * PP + pi];
        shj[tid] = g_h[n * PP + pj];
    }
    __syncthreads();
    for (int e = tid; e < 64 * 64; e += 256) {
        int i = e >> 6, j = e & 63;
        float a = shi[i] + shj[j];
#pragma unroll
        for (int d = 0; d < 5; ++d) a = fmaf(sfi[d][i], sfj[d][j], a);
        tile[i][j] = __expf(a);
    }
    __syncthreads();
    size_t base = (size_t)n * PP * PP;
    for (int e = tid; e < 64 * 64; e += 256) {
        int i = e >> 6, j = e & 63;
        g_K[base + (size_t)(bi * 64 + i) * PP + (bj * 64 + j)] = tile[i][j];
    }
    if (bi != bj) {
        for (int e = tid; e < 64 * 64; e += 256) {
            int i = e >> 6, j = e & 63;
            g_K[base + (size_t)(bj * 64 + i) * PP + (bi * 64 + j)] = tile[j][i];
        }
    }
}

// ---------------- softmax / update: q = softmax(U [+ 4 qbf + 2 qsf]) ----------------
__global__ void k_softmax(int usebq, float* __restrict__ extout) {
    int t = blockIdx.x * blockDim.x + threadIdx.x;
    if (t >= NB * PP) return;
    int n = t >> 12, p = t & 4095;
    float v[NC];
    float m = -1e30f;
#pragma unroll
    for (int c = 0; c < NC; ++c) {
        int idx = (n * NC + c) * PP + p;
        float a = g_U[idx];
        if (usebq) a = a + 4.0f * g_qbf[idx] + 2.0f * g_qsf[idx];
        v[c] = a;
        m = fmaxf(m, a);
    }
    float s = 0.f;
#pragma unroll
    for (int c = 0; c < NC; ++c) {
        v[c] = __expf(v[c] - m);
        s += v[c];
    }
    float inv = 1.0f / s;
#pragma unroll
    for (int c = 0; c < NC; ++c) {
        int idx = (n * NC + c) * PP + p;
        float r = v[c] * inv;
        g_q[idx] = r;
        if (extout) extout[idx] = r;
    }
}

// ---------------- GEMM: qbf[n][c][p] = sum_q K[n][p][q] * q[n][c][q] ----------------
// 128 thr/CTA, each warp owns 4 p-rows, lanes split q in float4 chunks,
// packed f32x2 accumulation, warp shuffle reduction.
__global__ void __launch_bounds__(128) k_gemm() {
    int n = blockIdx.y;
    int warp = blockIdx.x * 4 + (threadIdx.x >> 5);
    int lane = threadIdx.x & 31;
    int pbase = warp * 4;

    const float4* Kr0 = (const float4*)(g_K + (size_t)n * PP * PP + (size_t)(pbase + 0) * PP);
    const float4* Kr1 = (const float4*)(g_K + (size_t)n * PP * PP + (size_t)(pbase + 1) * PP);
    const float4* Kr2 = (const float4*)(g_K + (size_t)n * PP * PP + (size_t)(pbase + 2) * PP);
    const float4* Kr3 = (const float4*)(g_K + (size_t)n * PP * PP + (size_t)(pbase + 3) * PP);
    const float4* qb = (const float4*)(g_q + n * NC * PP);

    float2 acc[4][NC];
#pragma unroll
    for (int i = 0; i < 4; ++i)
#pragma unroll
        for (int c = 0; c < NC; ++c) acc[i][c] = make_float2(0.f, 0.f);

    for (int qc = 0; qc < 32; ++qc) {
        int off = qc * 32 + lane;
        float4 w0 = Kr0[off];
        float4 w1 = Kr1[off];
        float4 w2 = Kr2[off];
        float4 w3 = Kr3[off];
#pragma unroll
        for (int c = 0; c < NC; ++c) {
            float4 qv = qb[c * (PP / 4) + off];
            fma2(acc[0][c], w0.x, w0.y, qv.x, qv.y);
            fma2(acc[0][c], w0.z, w0.w, qv.z, qv.w);
            fma2(acc[1][c], w1.x, w1.y, qv.x, qv.y);
            fma2(acc[1][c], w1.z, w1.w, qv.z, qv.w);
            fma2(acc[2][c], w2.x, w2.y, qv.x, qv.y);
            fma2(acc[2][c], w2.z, w2.w, qv.z, qv.w);
            fma2(acc[3][c], w3.x, w3.y, qv.x, qv.y);
            fma2(acc[3][c], w3.z, w3.w, qv.z, qv.w);
        }
    }

#pragma unroll
    for (int i = 0; i < 4; ++i) {
#pragma unroll
        for (int c = 0; c < NC; ++c) {
            float s = acc[i][c].x + acc[i][c].y;
#pragma unroll
            for (int o = 16; o; o >>= 1) s += __shfl_xor_sync(0xFFFFFFFFu, s, o);
            if (lane == 0) g_qbf[(n * NC + c) * PP + pbase + i] = s;
        }
    }
}

// ---------------- separable 71x71 depthwise conv (one CTA per (n,c) plane) ----------------
__global__ void k_conv() {
    __shared__ float sin_[PP];
    __shared__ float stmp[PP];
    __shared__ float sg[KS];
    int c = blockIdx.x, n = blockIdx.y;
    int tid = threadIdx.x;
    if (tid < KS) sg[tid] = g_g1d[tid];
    const float* src = g_q + (n * NC + c) * PP;
    for (int i = tid; i < PP; i += 256) sin_[i] = src[i];
    __syncthreads();
    // horizontal pass
    for (int e = tid; e < PP; e += 256) {
        int y = e >> 6, x = e & 63;
        int lo = max(0, x - KR), hi = min(63, x + KR);
        float a = 0.f;
        for (int xx = lo; xx <= hi; ++xx) a = fmaf(sg[KR + xx - x], sin_[(y << 6) | xx], a);
        stmp[e] = a;
    }
    __syncthreads();
    // vertical pass
    float* dst = g_qsf + (n * NC + c) * PP;
    for (int e = tid; e < PP; e += 256) {
        int y = e >> 6, x = e & 63;
        int lo = max(0, y - KR), hi = min(63, y + KR);
        float a = 0.f;
        for (int yy = lo; yy <= hi; ++yy) a = fmaf(sg[KR + yy - y], stmp[(yy << 6) | x], a);
        dst[e] = a;
    }
}

// ---------------- launch ----------------
extern "C" void kernel_launch(void* const* d_in, const int* in_sizes, int n_in,
                              void* d_out, int out_size) {
    (void)in_sizes; (void)n_in; (void)out_size;
    const float* unary = (const float*)d_in[0];
    const float* ref   = (const float*)d_in[1];
    const float* gk    = (const float*)d_in[2];
    const float* kstd  = (const float*)d_in[3];
    float* out = (float*)d_out;

    k_prep<<<(NB * PP + 255) / 256, 256>>>(ref, kstd);
    k_logU<<<(NB * NC * PP + 255) / 256, 256>>>(unary);
    k_g1d<<<1, 128>>>(gk);
    k_buildK<<<dim3(64, 64, NB), 256>>>();

    k_softmax<<<(NB * PP + 255) / 256, 256>>>(0, nullptr);  // q0 = softmax(U)
    for (int it = 0; it < 5; ++it) {
        k_gemm<<<dim3(256, NB), 128>>>();
        k_conv<<<dim3(NC, NB), 256>>>();
        bool last = (it == 4);
        k_softmax<<<(NB * PP + 255) / 256, 256>>>(1, last ? out : nullptr);
    }
}